// round 4
// baseline (speedup 1.0000x reference)
#include <cuda_runtime.h>
#include <cuda_bf16.h>

#define BATCH 32
#define SEQT  512
#define INP   1024
#define HID   512
#define G     2048          // 4*HID
#define NC    4
#define RNK   8
#define SCALING 2.0f
#define HPAD  516           // HID + 4 floats pad (bank-conflict avoidance)

// -------------------- device scratch (no allocations allowed) --------------------
__device__ float g_weff_ih[(size_t)NC * G * INP];   // 32 MB
__device__ float g_weff_hh[(size_t)NC * G * HID];   // 16 MB
__device__ float g_gx[2ull * BATCH * SEQT * G];     // 268 MB (2 cells of current layer)
__device__ float g_l0out[(size_t)BATCH * SEQT * 2 * HID]; // 64 MB layer-0 output
__device__ float g_hbuf[2][2][BATCH * HID];         // [dir][pingpong]
__device__ unsigned g_bar[2];
__device__ unsigned g_gen[2];

// -------------------- weight folding: W_eff = W + SCALING * Bl @ A --------------------
__global__ void prep_weff_ih(const float* __restrict__ w, const float* __restrict__ a,
                             const float* __restrict__ bl)
{
    size_t idx = (size_t)blockIdx.x * 256 + threadIdx.x;
    const size_t total = (size_t)NC * G * INP;
    if (idx >= total) return;
    int d = (int)(idx % INP);
    int g = (int)((idx / INP) % G);
    int c = (int)(idx / ((size_t)INP * G));
    const float* ar  = a  + (size_t)c * RNK * INP + d;
    const float* blr = bl + ((size_t)c * G + g) * RNK;
    float acc = 0.f;
#pragma unroll
    for (int r = 0; r < RNK; r++) acc += blr[r] * ar[(size_t)r * INP];
    g_weff_ih[idx] = w[idx] + SCALING * acc;
}

__global__ void prep_weff_hh(const float* __restrict__ w, const float* __restrict__ a,
                             const float* __restrict__ bl)
{
    size_t idx = (size_t)blockIdx.x * 256 + threadIdx.x;
    const size_t total = (size_t)NC * G * HID;
    if (idx >= total) return;
    int d = (int)(idx % HID);
    int g = (int)((idx / HID) % G);
    int c = (int)(idx / ((size_t)HID * G));
    const float* ar  = a  + (size_t)c * RNK * HID + d;
    const float* blr = bl + ((size_t)c * G + g) * RNK;
    float acc = 0.f;
#pragma unroll
    for (int r = 0; r < RNK; r++) acc += blr[r] * ar[(size_t)r * HID];
    g_weff_hh[idx] = w[idx] + SCALING * acc;
}

// -------------------- gx GEMM: C[m][n] = sum_k A[m][k]*Weff[n][k] + bias[n] --------------------
// A: (BATCH*SEQT, INP) row-major; Weff: (G, INP) row-major (NT gemm, both K-contiguous)
__global__ __launch_bounds__(256) void gemm_gx(const float* __restrict__ Aext, int layer,
                                               const float* __restrict__ b_ih,
                                               const float* __restrict__ b_hh)
{
    __shared__ float As[16][132];
    __shared__ float Bs[16][132];

    const float* A = layer ? (const float*)g_l0out : Aext;
    const int cellL = blockIdx.z;          // 0/1 = dir within layer
    const int cell  = layer * 2 + cellL;
    const float* W  = g_weff_ih + (size_t)cell * G * INP;

    const int m0 = blockIdx.y * 128;
    const int n0 = blockIdx.x * 128;
    const int tid = threadIdx.x;
    const int tx = tid & 15, ty = tid >> 4;

    float acc[8][8];
#pragma unroll
    for (int i = 0; i < 8; i++)
#pragma unroll
        for (int j = 0; j < 8; j++) acc[i][j] = 0.f;

    for (int k0 = 0; k0 < INP; k0 += 16) {
#pragma unroll
        for (int i = 0; i < 2; i++) {
            int idx = tid + i * 256;
            int row = idx >> 2;
            int c4  = (idx & 3) * 4;
            float4 va = *(const float4*)(A + (size_t)(m0 + row) * INP + k0 + c4);
            As[c4 + 0][row] = va.x; As[c4 + 1][row] = va.y;
            As[c4 + 2][row] = va.z; As[c4 + 3][row] = va.w;
            float4 vb = *(const float4*)(W + (size_t)(n0 + row) * INP + k0 + c4);
            Bs[c4 + 0][row] = vb.x; Bs[c4 + 1][row] = vb.y;
            Bs[c4 + 2][row] = vb.z; Bs[c4 + 3][row] = vb.w;
        }
        __syncthreads();
#pragma unroll
        for (int k = 0; k < 16; k++) {
            float af[8], bf[8];
            *(float4*)(af + 0) = *(const float4*)&As[k][ty * 8];
            *(float4*)(af + 4) = *(const float4*)&As[k][ty * 8 + 4];
            *(float4*)(bf + 0) = *(const float4*)&Bs[k][tx * 8];
            *(float4*)(bf + 4) = *(const float4*)&Bs[k][tx * 8 + 4];
#pragma unroll
            for (int i = 0; i < 8; i++)
#pragma unroll
                for (int j = 0; j < 8; j++)
                    acc[i][j] = fmaf(af[i], bf[j], acc[i][j]);
        }
        __syncthreads();
    }

    float bias[8];
#pragma unroll
    for (int j = 0; j < 8; j++) {
        int n = n0 + tx * 8 + j;
        bias[j] = b_ih[cell * G + n] + b_hh[cell * G + n];
    }
    float* Cb = g_gx + (size_t)cellL * BATCH * SEQT * G;
#pragma unroll
    for (int i = 0; i < 8; i++) {
        float* dst = Cb + (size_t)(m0 + ty * 8 + i) * G + n0 + tx * 8;
        float4 v0 = make_float4(acc[i][0] + bias[0], acc[i][1] + bias[1],
                                acc[i][2] + bias[2], acc[i][3] + bias[3]);
        float4 v1 = make_float4(acc[i][4] + bias[4], acc[i][5] + bias[5],
                                acc[i][6] + bias[6], acc[i][7] + bias[7]);
        ((float4*)dst)[0] = v0;
        ((float4*)dst)[1] = v1;
    }
}

// -------------------- barrier reset --------------------
__global__ void reset_bar()
{
    if (threadIdx.x < 2) { g_bar[threadIdx.x] = 0u; g_gen[threadIdx.x] = 0u; }
}

__device__ __forceinline__ float sigm(float x) { return 1.f / (1.f + __expf(-x)); }

// inline function (NOT a macro) — avoids token substitution of struct field names
__device__ __forceinline__ void dot4(float& acc, const float4 hv, const float4 wv)
{
    acc = fmaf(hv.x, wv.x, fmaf(hv.y, wv.y, fmaf(hv.z, wv.z, fmaf(hv.w, wv.w, acc))));
}

// -------------------- persistent recurrence kernel --------------------
// grid = 128 CTAs: CTA>>6 = direction, CTA&63 selects 8 hidden units.
// smem: W_hh slice (32 gate rows x 512, padded) + h_prev (32 x 512, padded) = 132 KB.
__global__ __launch_bounds__(128, 1) void lstm_rec(int layer, float* __restrict__ dout)
{
    extern __shared__ float sm[];
    float* sW = sm;                 // 32*HPAD
    float* sH = sm + 32 * HPAD;     // 32*HPAD

    const int cta  = blockIdx.x;
    const int dir  = cta >> 6;
    const int cg   = cta & 63;
    const int j0   = cg * 8;
    const int cell = layer * 2 + dir;
    const int tid  = threadIdx.x;

    // Load persistent W_hh_eff slice: row r = gate*8 + u -> weff_hh[cell][gate*HID + j0+u][:]
    {
        const float* wbase = g_weff_hh + (size_t)cell * G * HID;
#pragma unroll
        for (int r = 0; r < 32; r++) {
            int gate = r >> 3, u = r & 7;
            const float4* src = (const float4*)(wbase + (size_t)(gate * HID + j0 + u) * HID);
            ((float4*)(sW + r * HPAD))[tid] = src[tid];
        }
    }
    for (int i = tid; i < 32 * HPAD; i += 128) sH[i] = 0.f;  // h_0 = 0
    __syncthreads();

    const int bp = tid >> 3;
    const int u  = tid & 7;
    const int b0 = bp * 2, b1 = b0 + 1;
    const int j  = j0 + u;
    const float* gx = g_gx + (size_t)dir * BATCH * SEQT * G;
    float* outbuf = layer ? dout : (float*)g_l0out;

    const float4* hp0 = (const float4*)(sH + b0 * HPAD);
    const float4* hp1 = (const float4*)(sH + b1 * HPAD);
    const float4* wvi = (const float4*)(sW + (0  + u) * HPAD);
    const float4* wvf = (const float4*)(sW + (8  + u) * HPAD);
    const float4* wvg = (const float4*)(sW + (16 + u) * HPAD);
    const float4* wvo = (const float4*)(sW + (24 + u) * HPAD);

    float c0 = 0.f, c1 = 0.f, h0v = 0.f, h1v = 0.f;

    for (int s = 0; s < SEQT; s++) {
        const int t = dir ? (SEQT - 1 - s) : s;

        if (s > 0) {
            // stage h(s-1) from the ping-pong global buffer into smem
            const float4* src = (const float4*)&g_hbuf[dir][(s - 1) & 1][0];
            for (int i = tid; i < (BATCH * HID) / 4; i += 128) {
                int bb = i >> 7, kk = i & 127;
                ((float4*)(sH + bb * HPAD))[kk] = src[i];
            }
            __syncthreads();
        }

        float ai0 = 0.f, af0 = 0.f, ag0 = 0.f, ao0 = 0.f;
        float ai1 = 0.f, af1 = 0.f, ag1 = 0.f, ao1 = 0.f;
#pragma unroll 4
        for (int kk = 0; kk < HID / 4; kk++) {
            float4 hv0 = hp0[kk], hv1 = hp1[kk];
            float4 vi = wvi[kk], vf = wvf[kk], vg = wvg[kk], vo = wvo[kk];
            dot4(ai0, hv0, vi); dot4(af0, hv0, vf); dot4(ag0, hv0, vg); dot4(ao0, hv0, vo);
            dot4(ai1, hv1, vi); dot4(af1, hv1, vf); dot4(ag1, hv1, vg); dot4(ao1, hv1, vo);
        }

        size_t gxo0 = ((size_t)(b0 * SEQT + t)) * G + j;
        size_t gxo1 = ((size_t)(b1 * SEQT + t)) * G + j;
        float gi0 = ai0 + gx[gxo0];
        float gf0 = af0 + gx[gxo0 + 512];
        float gg0 = ag0 + gx[gxo0 + 1024];
        float go0 = ao0 + gx[gxo0 + 1536];
        float gi1 = ai1 + gx[gxo1];
        float gf1 = af1 + gx[gxo1 + 512];
        float gg1 = ag1 + gx[gxo1 + 1024];
        float go1 = ao1 + gx[gxo1 + 1536];

        c0  = sigm(gf0) * c0 + sigm(gi0) * tanhf(gg0);
        h0v = sigm(go0) * tanhf(c0);
        c1  = sigm(gf1) * c1 + sigm(gi1) * tanhf(gg1);
        h1v = sigm(go1) * tanhf(c1);

        float* hb = &g_hbuf[dir][s & 1][0];
        hb[b0 * HID + j] = h0v;
        hb[b1 * HID + j] = h1v;
        outbuf[((size_t)b0 * SEQT + t) * (2 * HID) + dir * HID + j] = h0v;
        outbuf[((size_t)b1 * SEQT + t) * (2 * HID) + dir * HID + j] = h1v;

        if (s < SEQT - 1) {
            __syncthreads();                 // all CTA threads done writing h(s)
            if (tid == 0) {
                __threadfence();             // publish our h writes device-wide
                unsigned arr = atomicAdd(&g_bar[dir], 1u);
                if (arr == 63u) {
                    atomicExch(&g_bar[dir], 0u);
                    __threadfence();
                    atomicAdd(&g_gen[dir], 1u);
                } else {
                    unsigned target = (unsigned)(s + 1);
                    while (*((volatile unsigned*)&g_gen[dir]) < target) { }
                    __threadfence();
                }
            }
            __syncthreads();
        }
    }

    // final states: h_n / c_n, cells stacked [layer0d0, layer0d1, layer1d0, layer1d1]
    float* hn = dout + (size_t)BATCH * SEQT * 2 * HID;          // +16777216
    float* cn = hn + (size_t)NC * BATCH * HID;                  // +65536
    size_t o0 = ((size_t)cell * BATCH + b0) * HID + j;
    size_t o1 = ((size_t)cell * BATCH + b1) * HID + j;
    hn[o0] = h0v; hn[o1] = h1v;
    cn[o0] = c0;  cn[o1] = c1;
}

// -------------------- launch --------------------
extern "C" void kernel_launch(void* const* d_in, const int* in_sizes, int n_in,
                              void* d_out, int out_size)
{
    (void)in_sizes; (void)n_in; (void)out_size;
    const float* x     = (const float*)d_in[0];
    const float* w_ih  = (const float*)d_in[1];
    const float* w_hh  = (const float*)d_in[2];
    const float* b_ih  = (const float*)d_in[3];
    const float* b_hh  = (const float*)d_in[4];
    const float* a_ih  = (const float*)d_in[5];
    const float* bl_ih = (const float*)d_in[6];
    const float* a_hh  = (const float*)d_in[7];
    const float* bl_hh = (const float*)d_in[8];
    float* out = (float*)d_out;

    const int SMEM_REC = 64 * HPAD * (int)sizeof(float);  // 132096 B
    cudaFuncSetAttribute(lstm_rec, cudaFuncAttributeMaxDynamicSharedMemorySize, SMEM_REC);

    {
        size_t tih = (size_t)NC * G * INP;
        prep_weff_ih<<<(unsigned)((tih + 255) / 256), 256>>>(w_ih, a_ih, bl_ih);
        size_t thh = (size_t)NC * G * HID;
        prep_weff_hh<<<(unsigned)((thh + 255) / 256), 256>>>(w_hh, a_hh, bl_hh);
    }

    // ---- layer 0 ----
    gemm_gx<<<dim3(16, 128, 2), 256>>>(x, 0, b_ih, b_hh);
    reset_bar<<<1, 32>>>();
    lstm_rec<<<128, 128, SMEM_REC>>>(0, out);

    // ---- layer 1 ----
    gemm_gx<<<dim3(16, 128, 2), 256>>>(nullptr, 1, b_ih, b_hh);
    reset_bar<<<1, 32>>>();
    lstm_rec<<<128, 128, SMEM_REC>>>(1, out);
}